// round 1
// baseline (speedup 1.0000x reference)
#include <cuda_runtime.h>
#include <cstddef>

// Problem constants (fixed by reference)
#define N_KC   200
#define N_MBON 20
#define N_FBN  60
#define N_DAN  20
#define N_REC  100
#define N_EXT  2
#define T_TOT  61
#define T_STEPS 60
#define KPT    7          // ceil(200/32) columns per lane per row
#define NTHREADS 320
#define WM_CHUNK 34       // W_recur cols per thread-group

// smem layout (floats)
//  s_rk   : 12200   (full r_kc[b] slab, layout [k*61 + t])
//  s_r    : 104     (current r, padded with zeros to 104)
//  s_I    : 100     (I_tot: [0,20)=I_kc [20,80)=I_fbn [80,100)=0)
//  s_wrp  : 300     (Wr partial sums, 3 groups)
//  s_rbk  : 200
//  s_rbd  : 20
//  s_bias : 100
//  s_wro  : 20
//  s_wext : 120
#define SM_FLOATS (12200 + 104 + 100 + 300 + 200 + 20 + 100 + 20 + 120)

__global__ __launch_bounds__(NTHREADS, 2)
void cond_rnn_kernel(const float* __restrict__ r_kc,
                     const float* __restrict__ r_ext,
                     const float* __restrict__ timev,
                     const float* __restrict__ W0,
                     const float* __restrict__ wt0,
                     const float* __restrict__ W_recur,
                     const float* __restrict__ W_ext,
                     const float* __restrict__ W_readout,
                     const float* __restrict__ bias,
                     float* __restrict__ out,
                     int B)
{
    extern __shared__ float sm[];
    float* s_rk   = sm;
    float* s_r    = s_rk + 12200;
    float* s_I    = s_r + 104;
    float* s_wrp  = s_I + 100;
    float* s_rbk  = s_wrp + 300;
    float* s_rbd  = s_rbk + 200;
    float* s_bias = s_rbd + 20;
    float* s_wro  = s_bias + 100;
    float* s_wext = s_wro + 20;

    const int b    = blockIdx.x;
    const int tid  = threadIdx.x;
    const int w    = tid >> 5;     // warp id 0..9
    const int lane = tid & 31;

    const float dt = timev[1] - timev[0];
    const float cW = dt * (1.0f / 5.0f);  // dt / TAU_W
    const float cR = dt;                  // dt / TAU_R (TAU_R = 1)

    // output section offsets
    const size_t RALL = 0;
    const size_t WF   = (size_t)T_TOT * B * N_REC;
    const size_t WTF  = WF + (size_t)B * (N_MBON * N_KC);
    const size_t RO   = WTF + (size_t)B * (N_MBON * N_KC);

    // ---- stage r_kc[b] slab into smem (coalesced float4) ----
    const float* rkb = r_kc + (size_t)b * (N_KC * T_TOT);
    {
        const float4* src = (const float4*)rkb;
        float4* dst = (float4*)s_rk;
        for (int i = tid; i < (N_KC * T_TOT) / 4; i += NTHREADS) dst[i] = src[i];
    }

    // ---- init small shared state ----
    if (tid < 100) {
        s_bias[tid] = bias[tid];
        float r0 = (tid < N_MBON) ? 0.0f : 0.1f;
        s_r[tid] = r0;
        s_I[tid] = 0.0f;                      // DAN slice stays 0 forever
        out[RALL + (size_t)b * N_REC + tid] = r0;   // r_all[0]
    }
    if (tid >= 100 && tid < 104) s_r[tid] = 0.0f;   // zero pad for Wm chunks
    if (tid < 20) { s_wro[tid] = W_readout[tid]; s_rbd[tid] = 0.1f; }
    if (tid < 120) s_wext[tid] = W_ext[tid];
    if (tid < 200) s_rbk[tid] = rkb[tid * T_TOT];   // rbk0 = r_kc[:,:,0]
    if (tid == 0)  out[RO + b] = 0.0f;              // readout0 (MBON r is 0)

    // ---- plastic weights W / wt in registers: warp w owns rows (w, w+10) ----
    const int m1 = w;
    const int m2 = w + 10;
    float Wa[KPT], Wb_[KPT], wta[KPT], wtb[KPT];
    {
        const float* Wg  = W0  + (size_t)b * (N_MBON * N_KC);
        const float* wtg = wt0 + (size_t)b * (N_MBON * N_KC);
        #pragma unroll
        for (int i = 0; i < KPT; i++) {
            int k = lane + 32 * i;
            bool ok = (k < N_KC);
            Wa[i]  = ok ? Wg [m1 * N_KC + k] : 0.0f;
            Wb_[i] = ok ? Wg [m2 * N_KC + k] : 0.0f;
            wta[i] = ok ? wtg[m1 * N_KC + k] : 0.0f;
            wtb[i] = ok ? wtg[m2 * N_KC + k] : 0.0f;
        }
    }

    // ---- W_recur (masked -> Wm) in registers: thread (j = tid%100, g = tid/100) ----
    float wm[WM_CHUNK];
    const int jj = (tid < 300) ? (tid % 100) : 0;
    const int i0 = (tid < 300) ? (tid / 100) * WM_CHUNK : 0;
    if (tid < 300) {
        #pragma unroll
        for (int c = 0; c < WM_CHUNK; c++) {
            int i = i0 + c;
            float v = 0.0f;
            if (i < N_REC) {
                v = W_recur[jj * N_REC + i];
                if (jj < N_MBON && i >= N_REC - N_DAN) v = 0.0f; // Wm mask
            }
            wm[c] = v;
        }
    }

    __syncthreads();

    const float* rext_b = r_ext + (size_t)b * (N_EXT * T_TOT);

    for (int t = 0; t < T_STEPS; t++) {
        // ================= P0 =================
        // rk into regs + I_kc row dots
        float rk[KPT];
        #pragma unroll
        for (int i = 0; i < KPT; i++) {
            int k = lane + 32 * i;
            rk[i] = (k < N_KC) ? s_rk[k * T_TOT + t] : 0.0f;
        }
        float p1 = 0.0f, p2 = 0.0f;
        #pragma unroll
        for (int i = 0; i < KPT; i++) {
            p1 = fmaf(Wa[i],  rk[i], p1);
            p2 = fmaf(Wb_[i], rk[i], p2);
        }
        #pragma unroll
        for (int o = 16; o > 0; o >>= 1) {
            p1 += __shfl_xor_sync(0xFFFFFFFFu, p1, o);
            p2 += __shfl_xor_sync(0xFFFFFFFFu, p2, o);
        }
        if (lane == 0) { s_I[m1] = p1; s_I[m2] = p2; }

        // I_fbn
        if (tid < N_FBN) {
            float re0 = rext_b[t];
            float re1 = rext_b[T_TOT + t];
            s_I[N_MBON + tid] = fmaf(s_wext[tid * 2], re0, s_wext[tid * 2 + 1] * re1);
        }

        // Wr partials (reads old s_r)
        if (tid < 300) {
            float p = 0.0f;
            #pragma unroll
            for (int c = 0; c < WM_CHUNK; c++)
                p = fmaf(wm[c], s_r[i0 + c], p);
            s_wrp[tid] = p;
        }

        // rbk update (uses this step's rk)
        if (tid < N_KC) {
            float rbk = s_rbk[tid];
            float rkt = s_rk[tid * T_TOT + t];
            s_rbk[tid] = fmaf(rkt - rbk, cW, rbk);
        }
        __syncthreads();

        // ================= P1 =================
        if (tid < N_REC) {
            float x = s_wrp[tid] + s_wrp[100 + tid] + s_wrp[200 + tid]
                    + s_bias[tid] + s_I[tid];
            float rold = s_r[tid];
            float rn = fmaf(fmaxf(x, 0.0f) - rold, cR, rold);
            s_r[tid] = rn;
            out[RALL + ((size_t)(t + 1) * B + b) * N_REC + tid] = rn;
            if (tid >= N_REC - N_DAN) {
                int d = tid - (N_REC - N_DAN);
                float rbd = s_rbd[d];
                s_rbd[d] = fmaf(rn - rbd, cW, rbd);
            }
        }
        __syncthreads();

        // ================= P2 =================
        // plasticity update (register resident W/wt)
        float rbd1  = s_rbd[m1],        rbd2  = s_rbd[m2];
        float rdan1 = s_r[80 + m1],     rdan2 = s_r[80 + m2];
        #pragma unroll
        for (int i = 0; i < KPT; i++) {
            int k = lane + 32 * i;
            if (k < N_KC) {
                float rbk = s_rbk[k];
                float dw1 = fmaf(rbd1, rk[i], -(rdan1 * rbk));
                wta[i] = fmaf(dw1, dt, wta[i]);
                Wa[i]  = fminf(fmaxf(fmaf(wta[i] - Wa[i], cW, Wa[i]), 0.0f), 0.05f);
                float dw2 = fmaf(rbd2, rk[i], -(rdan2 * rbk));
                wtb[i] = fmaf(dw2, dt, wtb[i]);
                Wb_[i] = fminf(fmaxf(fmaf(wtb[i] - Wb_[i], cW, Wb_[i]), 0.0f), 0.05f);
            }
        }

        // readout (warp 0)
        if (w == 0) {
            float v = (lane < N_MBON) ? s_r[lane] * s_wro[lane] : 0.0f;
            #pragma unroll
            for (int o = 16; o > 0; o >>= 1)
                v += __shfl_xor_sync(0xFFFFFFFFu, v, o);
            if (lane == 0) out[RO + (size_t)(t + 1) * B + b] = v;
        }
        __syncthreads();   // protect s_rbk / s_wrp / s_I for next P0
    }

    // ---- final W / wt ----
    {
        float* Wf  = out + WF  + (size_t)b * (N_MBON * N_KC);
        float* wtf = out + WTF + (size_t)b * (N_MBON * N_KC);
        #pragma unroll
        for (int i = 0; i < KPT; i++) {
            int k = lane + 32 * i;
            if (k < N_KC) {
                Wf [m1 * N_KC + k] = Wa[i];
                Wf [m2 * N_KC + k] = Wb_[i];
                wtf[m1 * N_KC + k] = wta[i];
                wtf[m2 * N_KC + k] = wtb[i];
            }
        }
    }
}

extern "C" void kernel_launch(void* const* d_in, const int* in_sizes, int n_in,
                              void* d_out, int out_size) {
    const float* r_kc      = (const float*)d_in[0];
    const float* r_ext     = (const float*)d_in[1];
    const float* timev     = (const float*)d_in[2];
    const float* W0        = (const float*)d_in[3];
    const float* wt0       = (const float*)d_in[4];
    const float* W_recur   = (const float*)d_in[5];
    const float* W_ext     = (const float*)d_in[6];
    const float* W_readout = (const float*)d_in[7];
    const float* bias      = (const float*)d_in[8];
    float* out = (float*)d_out;

    int B = in_sizes[0] / (N_KC * T_TOT);

    static bool attr_set = false;
    if (!attr_set) {
        cudaFuncSetAttribute(cond_rnn_kernel,
                             cudaFuncAttributeMaxDynamicSharedMemorySize,
                             SM_FLOATS * sizeof(float));
        attr_set = true;
    }

    cond_rnn_kernel<<<B, NTHREADS, SM_FLOATS * sizeof(float)>>>(
        r_kc, r_ext, timev, W0, wt0, W_recur, W_ext, W_readout, bias, out, B);
}